// round 12
// baseline (speedup 1.0000x reference)
#include <cuda_runtime.h>
#include <cstdint>

#define A_TOTAL   8649        // 31*31*9
#define BATCH_N   64
#define PRE_TOPN  6000
#define POST_TOPN 1500
#define NT        256
#define NSLOT     24          // ceil(6000/256) — used only for the rank permute
#define NWARP     8
#define NCHUNK    24          // ceil(6000/256)
#define NBUCKET   4096

struct NmsScratch {           // lives in the dead ckey region after phase 2c
    float4 abox[POST_TOPN];   // accepted boxes, acceptance order
    float  a7[POST_TOPN];     // fmaf(0.7, area, 0.7e-9) per accepted box
    int    apos[POST_TOPN];   // accepted position (for score lookup)
    int    spos[NT];          // survivor positions for current chunk
    int    scnt;
    int    nacc;
};

struct Smem {
    float4             cbox[PRE_TOPN];     // staging order; becomes position order (rbox)
    union {
        unsigned long long ckey[PRE_TOPN]; // staging order; dead after phase 2c
        NmsScratch         nms;
    } u;
    int                inv[PRE_TOPN];      // rank->staging idx; then float scores (pos order)
    int                bidx[PRE_TOPN];     // phase-2b scratch
    int                hist[NBUCKET];      // radix hist / bucket hist / warp prefix
    unsigned long long prefix;
    int                kk;
    int                cnt;
};

__device__ __forceinline__ unsigned long long make_key(float s, int i) {
    // score descending, then original index ascending (matches jax top_k + argmax ties)
    return ((unsigned long long)__float_as_uint(s) << 32)
         | (unsigned long long)(0xFFFFFFFFu - (unsigned)i);
}

__device__ __forceinline__ int bucket_of(unsigned long long key) {
    float sc = __uint_as_float((unsigned)(key >> 32));
    int b = (int)(sc * (float)NBUCKET);
    return b > (NBUCKET - 1) ? (NBUCKET - 1) : b;
}

// Exact reference suppression test (verbatim expression/assoc order).
__device__ __forceinline__ bool exact_kill(const float4 sb, const float4 cb) {
    float y1 = fmaxf(sb.x, cb.x);
    float x1 = fmaxf(sb.y, cb.y);
    float y2 = fminf(sb.z, cb.z);
    float x2 = fminf(sb.w, cb.w);
    float inter = fmaxf(y2 - y1, 0.0f) * fmaxf(x2 - x1, 0.0f);
    float area_s = (sb.z - sb.x) * (sb.w - sb.y);
    float area_b = (cb.z - cb.x) * (cb.w - cb.y);
    float d = ((area_s + area_b) - inter) + 1e-9f;
    return (inter / d) > 0.7f;
}

extern __shared__ unsigned char smem_raw[];

__global__ void __launch_bounds__(NT, 1)
roibbox_kernel(const float* __restrict__ deltas,   // [B, A, 4]
               const float* __restrict__ probs,    // [B, A]
               const float* __restrict__ anchors,  // [A, 4]
               float* __restrict__ out_boxes,      // [B, 1500, 4]
               float* __restrict__ out_scores)     // [B, 1500]
{
    Smem* s = (Smem*)smem_raw;
    const int b    = blockIdx.x;
    const int tid  = threadIdx.x;
    const int warp = tid >> 5;
    const int lane = tid & 31;
    const unsigned fullm = 0xFFFFFFFFu;

    const float* pr = probs + (size_t)b * A_TOTAL;

    // ---------------- Phase 1: exact 6000th-largest key via byte radix-select ----------------
    if (tid == 0) { s->prefix = 0ULL; s->kk = PRE_TOPN; }
    __syncthreads();

    for (int pass = 0; pass < 8; ++pass) {
        const int shift = 56 - 8 * pass;
        if (tid < 256) s->hist[tid] = 0;
        __syncthreads();

        const unsigned long long pref = s->prefix;
        for (int i = tid; i < A_TOTAL; i += NT) {
            unsigned long long k = make_key(pr[i], i);
            bool match = (pass == 0) || ((k >> (shift + 8)) == pref);
            if (match) atomicAdd(&s->hist[(int)((k >> shift) & 255ULL)], 1);
        }
        __syncthreads();

        if (tid == 0) {
            int kk = s->kk;
            int cum = 0, bsel = 0;
            for (int bb = 255; bb >= 0; --bb) {
                int h = s->hist[bb];
                if (cum + h >= kk) { bsel = bb; s->kk = kk - cum; break; }
                cum += h;
            }
            s->prefix = (pref << 8) | (unsigned long long)bsel;
        }
        __syncthreads();
    }
    const unsigned long long thresh = s->prefix;

    // ---------------- Phase 2: compact top-6000 + decode boxes into SMEM ----------------------
    if (tid == 0) s->cnt = 0;
    __syncthreads();

    const float4* anc4 = (const float4*)anchors;
    const float4* del4 = (const float4*)(deltas + (size_t)b * A_TOTAL * 4);

    for (int i = tid; i < A_TOTAL; i += NT) {
        unsigned long long k = make_key(pr[i], i);
        if (k >= thresh) {
            int p = atomicAdd(&s->cnt, 1);
            float4 a = anc4[i];
            float4 d = del4[i];
            float anc_h = a.z - a.x;
            float anc_w = a.w - a.y;
            float acy   = a.x + 0.5f * anc_h;
            float acx   = a.y + 0.5f * anc_w;
            float h  = expf(d.z * 0.2f) * anc_h;
            float w  = expf(d.w * 0.2f) * anc_w;
            float cy = d.x * 0.1f * anc_h + acy;
            float cx = d.y * 0.1f * anc_w + acx;
            s->cbox[p] = make_float4(cy - 0.5f * h, cx - 0.5f * w,
                                     cy + 0.5f * h, cx + 0.5f * w);
            s->u.ckey[p] = k;
        }
    }
    __syncthreads();

    // ---------------- Phase 2b: exact rank of every candidate (desc key order) ----------------
    {
        const int CPT = NBUCKET / NT;  // 16
        const int base = tid * CPT;
        #pragma unroll
        for (int j = 0; j < CPT; ++j) s->hist[base + j] = 0;
        __syncthreads();

        for (int i = tid; i < PRE_TOPN; i += NT)
            atomicAdd(&s->hist[bucket_of(s->u.ckey[i])], 1);
        __syncthreads();

        int sum = 0;
        #pragma unroll
        for (int j = 0; j < CPT; ++j) {
            int v = s->hist[base + j];
            s->hist[base + j] = sum;
            sum += v;
        }
        s->bidx[tid] = sum;
        __syncthreads();
        if (tid == 0) {
            int run = 0;
            for (int i = 0; i < NT; ++i) { int v = s->bidx[i]; s->bidx[i] = run; run += v; }
        }
        __syncthreads();
        const int off = s->bidx[tid];
        #pragma unroll
        for (int j = 0; j < CPT; ++j) s->hist[base + j] += off;
        __syncthreads();

        for (int i = tid; i < PRE_TOPN; i += NT) {
            int bb = bucket_of(s->u.ckey[i]);
            int p  = atomicAdd(&s->hist[bb], 1);     // hist[b] becomes end-of-bucket
            s->bidx[p] = i;
        }
        __syncthreads();

        for (int i = tid; i < PRE_TOPN; i += NT) {
            unsigned long long k = s->u.ckey[i];
            int bb = bucket_of(k);
            int lo = (bb == 0) ? 0 : s->hist[bb - 1];
            int hi = s->hist[bb];
            int larger = 0;
            for (int j = lo; j < hi; ++j)
                larger += (s->u.ckey[s->bidx[j]] > k) ? 1 : 0;
            int rank = (PRE_TOPN - hi) + larger;     // higher bucket => smaller rank
            s->inv[rank] = i;
        }
        __syncthreads();
    }

    // -------- Phase 2c: permute cbox to position order via registers; build scores ------------
    float* const sk = (float*)s->inv;   // position-ordered scores (inv reused in place)
    {
        float4 box[NSLOT];
        #pragma unroll
        for (int k = 0; k < NSLOT; ++k) {
            int r = k * NT + tid;
            if (r < PRE_TOPN) {
                int si = s->inv[r];                              // read own inv entry
                box[k] = s->cbox[si];
                float sc = __uint_as_float((unsigned)(s->u.ckey[si] >> 32));
                sk[r] = sc;                                      // overwrite own inv entry
            }
        }
        __syncthreads();        // all scattered cbox/ckey reads complete
        #pragma unroll
        for (int k = 0; k < NSLOT; ++k) {
            int r = k * NT + tid;
            if (r < PRE_TOPN) s->cbox[r] = box[k];               // cbox now position-ordered
        }
    }
    __syncthreads();            // ckey region now dead -> NmsScratch may be written

    // ---------------- Phase 3: chunked sequential NMS (== greedy NMS on sorted list) ----------
    const float4* rbox = s->cbox;
    float4* abox = s->u.nms.abox;
    float*  a7   = s->u.nms.a7;
    int*    apos = s->u.nms.apos;

    if (tid == 0) s->u.nms.nacc = 0;
    __syncthreads();

    int naccTot = 0;
    for (int c = 0; c < NCHUNK && naccTot < POST_TOPN; ++c) {
        const int r = c * NT + tid;
        bool alive = (r < PRE_TOPN);
        float4 cb = make_float4(0.f, 0.f, 0.f, 0.f);
        float  ac7 = 0.f;
        if (alive) {
            cb = rbox[r];
            ac7 = 0.7f * ((cb.z - cb.x) * (cb.w - cb.y));
        }

        // ---- Phase A: test my candidate against all previously accepted boxes ----
        const int na = naccTot;       // uniform snapshot
        if (alive) {
            bool anyNear = false;
            #pragma unroll 4
            for (int a = 0; a < na; ++a) {
                float4 sb = abox[a];
                float dy = fminf(sb.z, cb.z) - fmaxf(sb.x, cb.x);
                float dx = fminf(sb.w, cb.w) - fmaxf(sb.y, cb.y);
                float inter = fmaxf(dy, 0.0f) * dx;        // one-sided clamp: safe for decision
                float cst = a7[a] + ac7;                   // 0.7*(aS+aB) + 0.7e-9
                float m = fmaf(1.7f, inter, -cst);         // == inter - 0.7*d (reals)
                float band = 1e-5f * cst;
                if (m > band) { alive = false; break; }    // certain kill
                anyNear = anyNear | (fabsf(m) <= band);
            }
            if (alive && anyNear) {                        // rare: exact re-check, full list
                for (int a = 0; a < na && alive; ++a) {
                    if (exact_kill(abox[a], cb)) alive = false;
                }
            }
        }

        // ---- stable survivor compaction (position order preserved) ----
        unsigned bal = __ballot_sync(fullm, alive);
        if (lane == 0) s->hist[warp] = __popc(bal);
        __syncthreads();
        if (tid == 0) {
            int run = 0;
            #pragma unroll
            for (int w = 0; w < NWARP; ++w) { int v = s->hist[w]; s->hist[w] = run; run += v; }
            s->u.nms.scnt = run;
        }
        __syncthreads();
        if (alive) {
            int idx = s->hist[warp] + __popc(bal & ((1u << lane) - 1u));
            s->u.nms.spos[idx] = r;
        }
        __syncthreads();

        // ---- Phase B: warp 0 resolves intra-chunk order serially ----
        if (warp == 0) {
            const int S = s->u.nms.scnt;
            float4  myb[8];
            float   my7[8];
            unsigned malive = 0;
            #pragma unroll
            for (int t = 0; t < 8; ++t) {
                int i = t * 32 + lane;
                myb[t] = make_float4(0.f, 0.f, 0.f, 0.f);
                my7[t] = 0.f;
                if (i < S) {
                    float4 bb = rbox[s->u.nms.spos[i]];
                    myb[t] = bb;
                    my7[t] = 0.7f * ((bb.z - bb.x) * (bb.w - bb.y));
                    malive |= (1u << t);
                }
            }
            int nacc = naccTot;
            for (int i = 0; i < S; ++i) {
                unsigned fl = __shfl_sync(fullm, (malive >> (i >> 5)) & 1u, i & 31);
                if (!fl) continue;
                int    rpos = s->u.nms.spos[i];
                float4 sb   = rbox[rpos];
                float  sa7  = fmaf(0.7f, (sb.z - sb.x) * (sb.w - sb.y), 0.7e-9f);
                if (lane == 0) { abox[nacc] = sb; a7[nacc] = sa7; apos[nacc] = rpos; }
                ++nacc;
                if (nacc == POST_TOPN) break;
                // suppress my survivors against sb (self dies via IoU=1)
                #pragma unroll
                for (int t = 0; t < 8; ++t) {
                    float4 c2 = myb[t];
                    float dy = fminf(sb.z, c2.z) - fmaxf(sb.x, c2.x);
                    float dx = fminf(sb.w, c2.w) - fmaxf(sb.y, c2.y);
                    float inter = fmaxf(dy, 0.0f) * dx;
                    float cst = sa7 + my7[t];
                    float m = fmaf(1.7f, inter, -cst);
                    float band = 1e-5f * cst;
                    bool kill;
                    if (fabsf(m) <= band) kill = exact_kill(sb, c2);   // rare
                    else                  kill = (m > 0.0f);
                    if (kill) malive &= ~(1u << t);
                }
            }
            if (lane == 0) s->u.nms.nacc = nacc;
        }
        __syncthreads();
        naccTot = s->u.nms.nacc;
    }

    // ---------------- Phase 4: emission (acceptance order == reference pick order) ------------
    float* ob = out_boxes  + (size_t)b * POST_TOPN * 4;
    float* os = out_scores + (size_t)b * POST_TOPN;

    for (int i = tid; i < POST_TOPN; i += NT) {
        if (i < naccTot) {
            float4 bx = abox[i];
            float4 o;
            o.x = fminf(fmaxf(bx.x, 0.0f), 1.0f);
            o.y = fminf(fmaxf(bx.y, 0.0f), 1.0f);
            o.z = fminf(fmaxf(bx.z, 0.0f), 1.0f);
            o.w = fminf(fmaxf(bx.w, 0.0f), 1.0f);
            ((float4*)ob)[i] = o;
            os[i] = sk[apos[i]];
        } else {
            ((float4*)ob)[i] = make_float4(0.f, 0.f, 0.f, 0.f);
            os[i] = 0.0f;
        }
    }
}

extern "C" void kernel_launch(void* const* d_in, const int* in_sizes, int n_in,
                              void* d_out, int out_size) {
    const float* deltas  = (const float*)d_in[0];   // [64,31,31,36] f32
    const float* probs   = (const float*)d_in[1];   // [64,31,31,9]  f32
    // d_in[2]: gt_labels int64 — unused
    const float* anchors = (const float*)d_in[3];   // [8649,4] f32

    float* out_boxes  = (float*)d_out;                                   // [64,1500,4]
    float* out_scores = (float*)d_out + (size_t)BATCH_N * POST_TOPN * 4; // [64,1500]

    const size_t smem_bytes = sizeof(Smem);
    cudaFuncSetAttribute(roibbox_kernel,
                         cudaFuncAttributeMaxDynamicSharedMemorySize,
                         (int)smem_bytes);

    roibbox_kernel<<<BATCH_N, NT, smem_bytes>>>(
        deltas, probs, anchors, out_boxes, out_scores);
}

// round 13
// speedup vs baseline: 2.1733x; 2.1733x over previous
#include <cuda_runtime.h>
#include <cstdint>

#define A_TOTAL   8649        // 31*31*9
#define BATCH_N   64
#define PRE_TOPN  6000
#define POST_TOPN 1500
#define NT        256
#define NSLOT     24          // ceil(6000/256)
#define NWARP     8
#define NBUCKET   4096
#define RINF      0x7FFFFFFFu
#define EPOCH     96          // picks between strided compactions
#define DEPOCH    32          // picks between dense re-densifications

struct Smem {
    float4             cbox[PRE_TOPN];       // staging order; becomes position order (rbox)
    unsigned long long ckey[PRE_TOPN];       // staging order; dead after phase 2c
    int                inv[PRE_TOPN];        // rank->staging idx; then float score buffer 0
    int                bidx[PRE_TOPN];       // phase-2b scratch; then float score buffer 1
    int                hist[NBUCKET];        // radix hist / bucket hist / compaction prefix
    alignas(16) unsigned wmin[2][NWARP];     // per-warp min position, double-buffered
    unsigned long long prefix;
    int                kk;
    int                cnt;
};

__device__ __forceinline__ unsigned long long make_key(float s, int i) {
    // score descending, then original index ascending (matches jax top_k + argmax ties)
    return ((unsigned long long)__float_as_uint(s) << 32)
         | (unsigned long long)(0xFFFFFFFFu - (unsigned)i);
}

__device__ __forceinline__ int bucket_of(unsigned long long key) {
    float sc = __uint_as_float((unsigned)(key >> 32));
    int b = (int)(sc * (float)NBUCKET);
    return b > (NBUCKET - 1) ? (NBUCKET - 1) : b;
}

// Exact reference suppression test (verbatim expression/assoc order).
__device__ __forceinline__ bool exact_kill(const float4 sb, const float4 cb) {
    float y1 = fmaxf(sb.x, cb.x);
    float x1 = fmaxf(sb.y, cb.y);
    float y2 = fminf(sb.z, cb.z);
    float x2 = fminf(sb.w, cb.w);
    float inter = fmaxf(y2 - y1, 0.0f) * fmaxf(x2 - x1, 0.0f);
    float area_s = (sb.z - sb.x) * (sb.w - sb.y);
    float area_b = (cb.z - cb.x) * (cb.w - cb.y);
    float d = ((area_s + area_b) - inter) + 1e-9f;
    return (inter / d) > 0.7f;
}

// One epoch of strided greedy NMS with compile-time live-slot count NS.
// Fast path m = 1.7*inter - cst (cst = 0.7*(aS+aB)+0.7e-9) with 1e-5*cst guard
// band + verbatim exact fallback: decisions bit-identical to the reference.
template<int NS>
__device__ __forceinline__ int run_epoch(
    Smem* __restrict__ s, const float* __restrict__ skCur,
    float4 (&box)[NSLOT], float (&ab7)[NSLOT], unsigned &mask,
    int t, int tEnd, float* __restrict__ ob, float* __restrict__ os,
    int tid, int lane, int warp, int &rc, bool &done)
{
    const float4* rbox = s->cbox;  // position-ordered boxes

    unsigned r_local = mask ? (unsigned)((__ffs((int)mask) - 1) * NT + tid) : RINF;
    while (true) {
        unsigned wr = __reduce_min_sync(0xFFFFFFFFu, r_local);
        if (lane == 0) s->wmin[rc & 1][warp] = wr;
        __syncthreads();

        const uint4* wm = (const uint4*)&s->wmin[rc & 1][0];
        uint4 v0 = wm[0], v1 = wm[1];
        unsigned m0 = min(min(v0.x, v0.y), min(v0.z, v0.w));
        unsigned m1 = min(min(v1.x, v1.y), min(v1.z, v1.w));
        unsigned rsel = min(m0, m1);
        ++rc;

        if (rsel == RINF) { done = true; return t; }

        const float4 sb = rbox[rsel];

        if (tid == 0) {
            float4 o;
            o.x = fminf(fmaxf(sb.x, 0.0f), 1.0f);
            o.y = fminf(fmaxf(sb.y, 0.0f), 1.0f);
            o.z = fminf(fmaxf(sb.z, 0.0f), 1.0f);
            o.w = fminf(fmaxf(sb.w, 0.0f), 1.0f);
            ((float4*)ob)[t] = o;
            os[t] = skCur[rsel];
        }
        ++t;
        if (t == POST_TOPN) { done = true; return t; }

        const float area_s = (sb.z - sb.x) * (sb.w - sb.y);
        const float as7    = fmaf(0.7f, area_s, 0.7e-9f);
        const unsigned mask0 = mask;
        bool anyNear = false;

        #pragma unroll
        for (int k = 0; k < NS; ++k) {
            float4 c = box[k];
            float dy = fminf(sb.z, c.z) - fmaxf(sb.x, c.x);
            float dx = fminf(sb.w, c.w) - fmaxf(sb.y, c.y);
            float inter = fmaxf(dy, 0.0f) * dx;
            float cst = as7 + ab7[k];
            float m = fmaf(1.7f, inter, -cst);
            if (m > 0.0f) mask &= ~(1u << k);
            anyNear = anyNear | (fabsf(m) <= 1e-5f * cst);
        }

        if (anyNear) {   // rare: redo with the exact reference expression
            mask = mask0;
            #pragma unroll
            for (int k = 0; k < NS; ++k) {
                if (exact_kill(sb, box[k])) mask &= ~(1u << k);
            }
        }

        r_local = mask ? (unsigned)((__ffs((int)mask) - 1) * NT + tid) : RINF;
        if (t == tEnd) return t;   // epoch boundary AFTER suppression for this pick
    }
}

extern __shared__ unsigned char smem_raw[];

__global__ void __launch_bounds__(NT, 1)
roibbox_kernel(const float* __restrict__ deltas,   // [B, A, 4]
               const float* __restrict__ probs,    // [B, A]
               const float* __restrict__ anchors,  // [A, 4]
               float* __restrict__ out_boxes,      // [B, 1500, 4]
               float* __restrict__ out_scores)     // [B, 1500]
{
    Smem* s = (Smem*)smem_raw;
    const int b    = blockIdx.x;
    const int tid  = threadIdx.x;
    const int warp = tid >> 5;
    const int lane = tid & 31;
    const unsigned fullm = 0xFFFFFFFFu;
    const unsigned lml = (1u << lane) - 1u;

    const float* pr = probs + (size_t)b * A_TOTAL;

    // ---------------- Phase 1: exact 6000th-largest key via byte radix-select ----------------
    if (tid == 0) { s->prefix = 0ULL; s->kk = PRE_TOPN; }
    __syncthreads();

    for (int pass = 0; pass < 8; ++pass) {
        const int shift = 56 - 8 * pass;
        if (tid < 256) s->hist[tid] = 0;
        __syncthreads();

        const unsigned long long pref = s->prefix;
        for (int i = tid; i < A_TOTAL; i += NT) {
            unsigned long long k = make_key(pr[i], i);
            bool match = (pass == 0) || ((k >> (shift + 8)) == pref);
            if (match) atomicAdd(&s->hist[(int)((k >> shift) & 255ULL)], 1);
        }
        __syncthreads();

        if (tid == 0) {
            int kk = s->kk;
            int cum = 0, bsel = 0;
            for (int bb = 255; bb >= 0; --bb) {
                int h = s->hist[bb];
                if (cum + h >= kk) { bsel = bb; s->kk = kk - cum; break; }
                cum += h;
            }
            s->prefix = (pref << 8) | (unsigned long long)bsel;
        }
        __syncthreads();
    }
    const unsigned long long thresh = s->prefix;

    // ---------------- Phase 2: compact top-6000 + decode boxes into SMEM ----------------------
    if (tid == 0) s->cnt = 0;
    __syncthreads();

    const float4* anc4 = (const float4*)anchors;
    const float4* del4 = (const float4*)(deltas + (size_t)b * A_TOTAL * 4);

    for (int i = tid; i < A_TOTAL; i += NT) {
        unsigned long long k = make_key(pr[i], i);
        if (k >= thresh) {
            int p = atomicAdd(&s->cnt, 1);
            float4 a = anc4[i];
            float4 d = del4[i];
            float anc_h = a.z - a.x;
            float anc_w = a.w - a.y;
            float acy   = a.x + 0.5f * anc_h;
            float acx   = a.y + 0.5f * anc_w;
            float h  = expf(d.z * 0.2f) * anc_h;
            float w  = expf(d.w * 0.2f) * anc_w;
            float cy = d.x * 0.1f * anc_h + acy;
            float cx = d.y * 0.1f * anc_w + acx;
            s->cbox[p] = make_float4(cy - 0.5f * h, cx - 0.5f * w,
                                     cy + 0.5f * h, cx + 0.5f * w);
            s->ckey[p] = k;
        }
    }
    __syncthreads();

    // ---------------- Phase 2b: exact rank of every candidate (desc key order) ----------------
    {
        const int CPT = NBUCKET / NT;  // 16
        const int base = tid * CPT;
        #pragma unroll
        for (int j = 0; j < CPT; ++j) s->hist[base + j] = 0;
        __syncthreads();

        for (int i = tid; i < PRE_TOPN; i += NT)
            atomicAdd(&s->hist[bucket_of(s->ckey[i])], 1);
        __syncthreads();

        int sum = 0;
        #pragma unroll
        for (int j = 0; j < CPT; ++j) {
            int v = s->hist[base + j];
            s->hist[base + j] = sum;
            sum += v;
        }
        s->bidx[tid] = sum;
        __syncthreads();
        if (tid == 0) {
            int run = 0;
            for (int i = 0; i < NT; ++i) { int v = s->bidx[i]; s->bidx[i] = run; run += v; }
        }
        __syncthreads();
        const int off = s->bidx[tid];
        #pragma unroll
        for (int j = 0; j < CPT; ++j) s->hist[base + j] += off;
        __syncthreads();

        for (int i = tid; i < PRE_TOPN; i += NT) {
            int bb = bucket_of(s->ckey[i]);
            int p  = atomicAdd(&s->hist[bb], 1);     // hist[b] becomes end-of-bucket
            s->bidx[p] = i;
        }
        __syncthreads();

        for (int i = tid; i < PRE_TOPN; i += NT) {
            unsigned long long k = s->ckey[i];
            int bb = bucket_of(k);
            int lo = (bb == 0) ? 0 : s->hist[bb - 1];
            int hi = s->hist[bb];
            int larger = 0;
            for (int j = lo; j < hi; ++j)
                larger += (s->ckey[s->bidx[j]] > k) ? 1 : 0;
            int rank = (PRE_TOPN - hi) + larger;     // higher bucket => smaller rank
            s->inv[rank] = i;
        }
        __syncthreads();
    }

    // ---------------- Phase 2c: registers in rank order; permute cbox in place; build scores --
    float* const skBuf0 = (float*)s->inv;    // score double-buffers (inv/bidx reused)
    float* const skBuf1 = (float*)s->bidx;

    float4 box[NSLOT];
    float  ab7[NSLOT];
    unsigned mask = 0;
    #pragma unroll
    for (int k = 0; k < NSLOT; ++k) {
        int r = k * NT + tid;
        if (r < PRE_TOPN) {
            int si = s->inv[r];
            float4 c = s->cbox[si];
            box[k] = c;
            ab7[k] = 0.7f * ((c.z - c.x) * (c.w - c.y));
            mask |= (1u << k);
            skBuf1[r] = __uint_as_float((unsigned)(s->ckey[si] >> 32));  // bidx is free
        } else {
            box[k] = make_float4(0.f, 0.f, 0.f, 0.f);
            ab7[k] = 0.f;
        }
    }
    __syncthreads();                 // all gathers (and inv reads) done before overwrite
    #pragma unroll
    for (int k = 0; k < NSLOT; ++k) {
        int r = k * NT + tid;
        if (r < PRE_TOPN) s->cbox[r] = box[k];   // cbox now position-ordered (rbox)
    }
    __syncthreads();

    // ---------------- Phase 3a: strided epoch loop while live > NT ----------------------------
    float* ob = out_boxes  + (size_t)b * POST_TOPN * 4;
    float* os = out_scores + (size_t)b * POST_TOPN;

    int t = 0, ns = NSLOT, cur = 1, rc = 0;   // scores currently in skBuf1
    int live = PRE_TOPN;
    bool done = false;

    while (!done) {
        const int tEnd = (t + EPOCH < POST_TOPN) ? (t + EPOCH) : POST_TOPN;
        const float* skCur = cur ? skBuf1 : skBuf0;

        switch (ns) {
            case 24: t = run_epoch<24>(s, skCur, box, ab7, mask, t, tEnd, ob, os, tid, lane, warp, rc, done); break;
            case 16: t = run_epoch<16>(s, skCur, box, ab7, mask, t, tEnd, ob, os, tid, lane, warp, rc, done); break;
            case 12: t = run_epoch<12>(s, skCur, box, ab7, mask, t, tEnd, ob, os, tid, lane, warp, rc, done); break;
            case  8: t = run_epoch< 8>(s, skCur, box, ab7, mask, t, tEnd, ob, os, tid, lane, warp, rc, done); break;
            case  4: t = run_epoch< 4>(s, skCur, box, ab7, mask, t, tEnd, ob, os, tid, lane, warp, rc, done); break;
            default: t = run_epoch< 2>(s, skCur, box, ab7, mask, t, tEnd, ob, os, tid, lane, warp, rc, done); break;
        }
        if (done) break;

        // ---- compaction: dense re-pack of live candidates (order preserved) ----
        float* skNext = cur ? skBuf0 : skBuf1;

        #pragma unroll
        for (int k = 0; k < NSLOT; ++k) {
            unsigned bal = __ballot_sync(fullm, (mask >> k) & 1u);
            if (lane == 0) s->hist[k * NWARP + warp] = __popc(bal);
        }
        __syncthreads();   // all threads done reading rbox/skCur this epoch
        if (tid == 0) {
            int run = 0;
            for (int i = 0; i < NSLOT * NWARP; ++i) { int v = s->hist[i]; s->hist[i] = run; run += v; }
            s->cnt = run;
        }
        __syncthreads();
        live = s->cnt;

        #pragma unroll
        for (int k = 0; k < NSLOT; ++k) {
            unsigned bit = (mask >> k) & 1u;
            unsigned bal = __ballot_sync(fullm, bit);
            if (bit) {
                int pos = s->hist[k * NWARP + warp] + __popc(bal & lml);
                skNext[pos]  = skCur[k * NT + tid];
                s->cbox[pos] = box[k];            // boxes re-packed from registers, in place
            }
        }
        __syncthreads();
        cur ^= 1;

        if (live <= NT) break;                    // switch to dense tail mode

        const int c = (live + NT - 1) / NT;
        ns = (c > 16) ? 24 : (c > 12) ? 16 : (c > 8) ? 12 : (c > 4) ? 8 : (c > 2) ? 4 : 2;
        mask = 0;
        #pragma unroll
        for (int k = 0; k < NSLOT; ++k) {
            int idx = k * NT + tid;
            if (k < ns && idx < live) {
                float4 cc = s->cbox[idx];
                box[k] = cc;
                ab7[k] = 0.7f * ((cc.z - cc.x) * (cc.w - cc.y));
                mask |= (1u << k);
            }
        }
    }

    // ---------------- Phase 3b: dense tail mode (1 candidate per thread) ----------------------
    if (!done) {
        const float4* rbox = s->cbox;
        float* skd = cur ? skBuf1 : skBuf0;       // current score buffer (position-ordered)

        bool   alive = (tid < live);
        float4 cb    = alive ? rbox[tid] : make_float4(0.f, 0.f, 0.f, 0.f);
        float  c7    = 0.7f * ((cb.z - cb.x) * (cb.w - cb.y));
        float  mysc  = alive ? skd[tid] : 0.0f;
        int    since = 0;

        while (true) {
            unsigned r_local = alive ? (unsigned)tid : RINF;
            unsigned wr = __reduce_min_sync(fullm, r_local);
            if (lane == 0) s->wmin[rc & 1][warp] = wr;
            __syncthreads();

            const uint4* wm = (const uint4*)&s->wmin[rc & 1][0];
            uint4 v0 = wm[0], v1 = wm[1];
            unsigned m0 = min(min(v0.x, v0.y), min(v0.z, v0.w));
            unsigned m1 = min(min(v1.x, v1.y), min(v1.z, v1.w));
            unsigned rsel = min(m0, m1);
            ++rc;

            if (rsel == RINF) break;

            const float4 sb = rbox[rsel];          // static between re-densifications

            if (tid == (int)rsel) {                // owner writes output from registers
                float4 o;
                o.x = fminf(fmaxf(cb.x, 0.0f), 1.0f);
                o.y = fminf(fmaxf(cb.y, 0.0f), 1.0f);
                o.z = fminf(fmaxf(cb.z, 0.0f), 1.0f);
                o.w = fminf(fmaxf(cb.w, 0.0f), 1.0f);
                ((float4*)ob)[t] = o;
                os[t] = mysc;
            }
            ++t;
            if (t == POST_TOPN) break;

            if (alive) {
                float sa7 = fmaf(0.7f, (sb.z - sb.x) * (sb.w - sb.y), 0.7e-9f);
                float dy = fminf(sb.z, cb.z) - fmaxf(sb.x, cb.x);
                float dx = fminf(sb.w, cb.w) - fmaxf(sb.y, cb.y);
                float inter = fmaxf(dy, 0.0f) * dx;
                float cst = sa7 + c7;
                float m = fmaf(1.7f, inter, -cst);
                if (fabsf(m) <= 1e-5f * cst) {     // rare: verbatim reference expression
                    if (exact_kill(sb, cb)) alive = false;
                } else if (m > 0.0f) {
                    alive = false;
                }
            }

            if (++since == DEPOCH) {               // uniform: re-densify
                since = 0;
                unsigned bal = __ballot_sync(fullm, alive);
                if (lane == 0) s->hist[warp] = __popc(bal);
                __syncthreads();                   // also: everyone done reading rbox/skd
                if (tid == 0) {
                    int run = 0;
                    #pragma unroll
                    for (int w = 0; w < NWARP; ++w) { int v = s->hist[w]; s->hist[w] = run; run += v; }
                    s->cnt = run;
                }
                __syncthreads();
                live = s->cnt;
                if (alive) {
                    int pos = s->hist[warp] + __popc(bal & lml);
                    s->cbox[pos] = cb;             // scatter from registers (stable pack)
                    skd[pos] = mysc;
                }
                __syncthreads();
                alive = (tid < live);
                cb    = alive ? rbox[tid] : make_float4(0.f, 0.f, 0.f, 0.f);
                c7    = 0.7f * ((cb.z - cb.x) * (cb.w - cb.y));
                mysc  = alive ? skd[tid] : 0.0f;
            }
        }
    }

    // zero-fill remaining slots (reference emits zeros once candidates are exhausted)
    for (int i = t * 4 + tid; i < POST_TOPN * 4; i += NT) ob[i] = 0.0f;
    for (int i = t + tid;     i < POST_TOPN;     i += NT) os[i] = 0.0f;
}

extern "C" void kernel_launch(void* const* d_in, const int* in_sizes, int n_in,
                              void* d_out, int out_size) {
    const float* deltas  = (const float*)d_in[0];   // [64,31,31,36] f32
    const float* probs   = (const float*)d_in[1];   // [64,31,31,9]  f32
    // d_in[2]: gt_labels int64 — unused
    const float* anchors = (const float*)d_in[3];   // [8649,4] f32

    float* out_boxes  = (float*)d_out;                                   // [64,1500,4]
    float* out_scores = (float*)d_out + (size_t)BATCH_N * POST_TOPN * 4; // [64,1500]

    const size_t smem_bytes = sizeof(Smem);
    cudaFuncSetAttribute(roibbox_kernel,
                         cudaFuncAttributeMaxDynamicSharedMemorySize,
                         (int)smem_bytes);

    roibbox_kernel<<<BATCH_N, NT, smem_bytes>>>(
        deltas, probs, anchors, out_boxes, out_scores);
}

// round 14
// speedup vs baseline: 2.2827x; 1.0503x over previous
#include <cuda_runtime.h>
#include <cstdint>

#define A_TOTAL   8649        // 31*31*9
#define BATCH_N   64
#define PRE_TOPN  6000
#define POST_TOPN 1500
#define NT        256
#define NSLOT     24          // ceil(6000/256)
#define NWARP     8
#define NBUCKET   4096
#define RINF      0x7FFFFFFFu
#define EPOCH     96          // picks between live-set compactions

struct Smem {
    float4             cbox[PRE_TOPN];       // staging order; becomes position order (rbox)
    unsigned long long ckey[PRE_TOPN];       // staging order; dead after phase 2c
    int                inv[PRE_TOPN];        // rank->staging idx; then float score buffer 0
    int                bidx[PRE_TOPN];       // phase-2b scratch; then float score buffer 1
    int                hist[NBUCKET];        // radix hist / bucket hist / compaction prefix
    alignas(16) unsigned wmin[2][NWARP];     // per-warp min position, double-buffered
    unsigned long long prefix;
    int                kk;
    int                cnt;
};

__device__ __forceinline__ unsigned long long make_key(float s, int i) {
    // score descending, then original index ascending (matches jax top_k + argmax ties)
    return ((unsigned long long)__float_as_uint(s) << 32)
         | (unsigned long long)(0xFFFFFFFFu - (unsigned)i);
}

__device__ __forceinline__ int bucket_of(unsigned long long key) {
    float sc = __uint_as_float((unsigned)(key >> 32));
    int b = (int)(sc * (float)NBUCKET);
    return b > (NBUCKET - 1) ? (NBUCKET - 1) : b;
}

// Exact reference suppression test (verbatim expression/assoc order).
__device__ __forceinline__ bool exact_kill(const float4 sb, const float4 cb) {
    float y1 = fmaxf(sb.x, cb.x);
    float x1 = fmaxf(sb.y, cb.y);
    float y2 = fminf(sb.z, cb.z);
    float x2 = fminf(sb.w, cb.w);
    float inter = fmaxf(y2 - y1, 0.0f) * fmaxf(x2 - x1, 0.0f);
    float area_s = (sb.z - sb.x) * (sb.w - sb.y);
    float area_b = (cb.z - cb.x) * (cb.w - cb.y);
    float d = ((area_s + area_b) - inter) + 1e-9f;
    return (inter / d) > 0.7f;
}

// One epoch of strided greedy NMS with compile-time live-slot count NS.
// Fast path m = 1.7*inter - cst (cst = 0.7*(aS+aB)+0.7e-9) with a 1e-5*cst guard
// band accumulated in FP (nearAcc); any in-band slot triggers a verbatim exact
// re-check of all slots, so suppression decisions are bit-identical to the
// reference inter/d > 0.7f.
template<int NS>
__device__ __forceinline__ int run_epoch(
    Smem* __restrict__ s, const float* __restrict__ skCur,
    float4 (&box)[NSLOT], float (&ab7)[NSLOT], unsigned &mask,
    int t, int tEnd, float* __restrict__ ob, float* __restrict__ os,
    int tid, int lane, int warp, int &rc, bool &done)
{
    const float4* rbox = s->cbox;  // position-ordered boxes

    unsigned r_local = mask ? (unsigned)((__ffs((int)mask) - 1) * NT + tid) : RINF;
    while (true) {
        unsigned wr = __reduce_min_sync(0xFFFFFFFFu, r_local);
        if (lane == 0) s->wmin[rc & 1][warp] = wr;
        __syncthreads();

        // global min via 2x LDS.128 + register min tree (all threads, uniform)
        const uint4* wm = (const uint4*)&s->wmin[rc & 1][0];
        uint4 v0 = wm[0], v1 = wm[1];
        unsigned m0 = min(min(v0.x, v0.y), min(v0.z, v0.w));
        unsigned m1 = min(min(v1.x, v1.y), min(v1.z, v1.w));
        unsigned rsel = min(m0, m1);
        ++rc;

        if (rsel == RINF) { done = true; return t; }

        const float4 sb = rbox[rsel];

        if (tid == 0) {
            float4 o;
            o.x = fminf(fmaxf(sb.x, 0.0f), 1.0f);
            o.y = fminf(fmaxf(sb.y, 0.0f), 1.0f);
            o.z = fminf(fmaxf(sb.z, 0.0f), 1.0f);
            o.w = fminf(fmaxf(sb.w, 0.0f), 1.0f);
            ((float4*)ob)[t] = o;
            os[t] = skCur[rsel];
        }
        ++t;
        if (t == POST_TOPN) { done = true; return t; }

        const float area_s = (sb.z - sb.x) * (sb.w - sb.y);
        const float as7    = fmaf(0.7f, area_s, 0.7e-9f);
        const unsigned mask0 = mask;
        float nearAcc = -1.0f;

        #pragma unroll
        for (int k = 0; k < NS; ++k) {
            float4 c = box[k];
            float dy = fminf(sb.z, c.z) - fmaxf(sb.x, c.x);
            float dx = fminf(sb.w, c.w) - fmaxf(sb.y, c.y);
            float inter = fmaxf(dy, 0.0f) * dx;          // one-sided clamp: decision-safe
            float cst = as7 + ab7[k];
            float m = fmaf(1.7f, inter, -cst);           // == inter - 0.7*d (reals)
            if (m > 0.0f) mask &= ~(1u << k);
            nearAcc = fmaxf(nearAcc, fmaf(1e-5f, cst, -fabsf(m)));
        }

        if (nearAcc >= 0.0f) {   // rare: redo with the exact reference expression
            mask = mask0;
            #pragma unroll
            for (int k = 0; k < NS; ++k) {
                if (exact_kill(sb, box[k])) mask &= ~(1u << k);
            }
        }

        r_local = mask ? (unsigned)((__ffs((int)mask) - 1) * NT + tid) : RINF;
        if (t == tEnd) return t;   // epoch boundary AFTER suppression for this pick
    }
}

extern __shared__ unsigned char smem_raw[];

__global__ void __launch_bounds__(NT, 1)
roibbox_kernel(const float* __restrict__ deltas,   // [B, A, 4]
               const float* __restrict__ probs,    // [B, A]
               const float* __restrict__ anchors,  // [A, 4]
               float* __restrict__ out_boxes,      // [B, 1500, 4]
               float* __restrict__ out_scores)     // [B, 1500]
{
    Smem* s = (Smem*)smem_raw;
    const int b    = blockIdx.x;
    const int tid  = threadIdx.x;
    const int warp = tid >> 5;
    const int lane = tid & 31;
    const unsigned fullm = 0xFFFFFFFFu;
    const unsigned lml = (1u << lane) - 1u;

    const float* pr = probs + (size_t)b * A_TOTAL;

    // ---------------- Phase 1: exact 6000th-largest key via byte radix-select ----------------
    if (tid == 0) { s->prefix = 0ULL; s->kk = PRE_TOPN; }
    __syncthreads();

    for (int pass = 0; pass < 8; ++pass) {
        const int shift = 56 - 8 * pass;
        if (tid < 256) s->hist[tid] = 0;
        __syncthreads();

        const unsigned long long pref = s->prefix;
        for (int i = tid; i < A_TOTAL; i += NT) {
            unsigned long long k = make_key(pr[i], i);
            bool match = (pass == 0) || ((k >> (shift + 8)) == pref);
            if (match) atomicAdd(&s->hist[(int)((k >> shift) & 255ULL)], 1);
        }
        __syncthreads();

        if (tid == 0) {
            int kk = s->kk;
            int cum = 0, bsel = 0;
            for (int bb = 255; bb >= 0; --bb) {
                int h = s->hist[bb];
                if (cum + h >= kk) { bsel = bb; s->kk = kk - cum; break; }
                cum += h;
            }
            s->prefix = (pref << 8) | (unsigned long long)bsel;
        }
        __syncthreads();
    }
    const unsigned long long thresh = s->prefix;

    // ---------------- Phase 2: compact top-6000 + decode boxes into SMEM ----------------------
    if (tid == 0) s->cnt = 0;
    __syncthreads();

    const float4* anc4 = (const float4*)anchors;
    const float4* del4 = (const float4*)(deltas + (size_t)b * A_TOTAL * 4);

    for (int i = tid; i < A_TOTAL; i += NT) {
        unsigned long long k = make_key(pr[i], i);
        if (k >= thresh) {
            int p = atomicAdd(&s->cnt, 1);
            float4 a = anc4[i];
            float4 d = del4[i];
            float anc_h = a.z - a.x;
            float anc_w = a.w - a.y;
            float acy   = a.x + 0.5f * anc_h;
            float acx   = a.y + 0.5f * anc_w;
            float h  = expf(d.z * 0.2f) * anc_h;
            float w  = expf(d.w * 0.2f) * anc_w;
            float cy = d.x * 0.1f * anc_h + acy;
            float cx = d.y * 0.1f * anc_w + acx;
            s->cbox[p] = make_float4(cy - 0.5f * h, cx - 0.5f * w,
                                     cy + 0.5f * h, cx + 0.5f * w);
            s->ckey[p] = k;
        }
    }
    __syncthreads();

    // ---------------- Phase 2b: exact rank of every candidate (desc key order) ----------------
    {
        const int CPT = NBUCKET / NT;  // 16
        const int base = tid * CPT;
        #pragma unroll
        for (int j = 0; j < CPT; ++j) s->hist[base + j] = 0;
        __syncthreads();

        for (int i = tid; i < PRE_TOPN; i += NT)
            atomicAdd(&s->hist[bucket_of(s->ckey[i])], 1);
        __syncthreads();

        int sum = 0;
        #pragma unroll
        for (int j = 0; j < CPT; ++j) {
            int v = s->hist[base + j];
            s->hist[base + j] = sum;
            sum += v;
        }
        s->bidx[tid] = sum;
        __syncthreads();
        if (tid == 0) {
            int run = 0;
            for (int i = 0; i < NT; ++i) { int v = s->bidx[i]; s->bidx[i] = run; run += v; }
        }
        __syncthreads();
        const int off = s->bidx[tid];
        #pragma unroll
        for (int j = 0; j < CPT; ++j) s->hist[base + j] += off;
        __syncthreads();

        for (int i = tid; i < PRE_TOPN; i += NT) {
            int bb = bucket_of(s->ckey[i]);
            int p  = atomicAdd(&s->hist[bb], 1);     // hist[b] becomes end-of-bucket
            s->bidx[p] = i;
        }
        __syncthreads();

        for (int i = tid; i < PRE_TOPN; i += NT) {
            unsigned long long k = s->ckey[i];
            int bb = bucket_of(k);
            int lo = (bb == 0) ? 0 : s->hist[bb - 1];
            int hi = s->hist[bb];
            int larger = 0;
            for (int j = lo; j < hi; ++j)
                larger += (s->ckey[s->bidx[j]] > k) ? 1 : 0;
            int rank = (PRE_TOPN - hi) + larger;     // higher bucket => smaller rank
            s->inv[rank] = i;
        }
        __syncthreads();
    }

    // ---------------- Phase 2c: registers in rank order; permute cbox in place; build scores --
    float* const skBuf0 = (float*)s->inv;    // score double-buffers (inv/bidx reused)
    float* const skBuf1 = (float*)s->bidx;

    float4 box[NSLOT];
    float  ab7[NSLOT];
    unsigned mask = 0;
    #pragma unroll
    for (int k = 0; k < NSLOT; ++k) {
        int r = k * NT + tid;
        if (r < PRE_TOPN) {
            int si = s->inv[r];
            float4 c = s->cbox[si];
            box[k] = c;
            ab7[k] = 0.7f * ((c.z - c.x) * (c.w - c.y));
            mask |= (1u << k);
            skBuf1[r] = __uint_as_float((unsigned)(s->ckey[si] >> 32));  // bidx is free
        } else {
            box[k] = make_float4(0.f, 0.f, 0.f, 0.f);
            ab7[k] = 0.f;
        }
    }
    __syncthreads();                 // all gathers (and inv reads) done before overwrite
    #pragma unroll
    for (int k = 0; k < NSLOT; ++k) {
        int r = k * NT + tid;
        if (r < PRE_TOPN) s->cbox[r] = box[k];   // cbox now position-ordered (rbox)
    }
    __syncthreads();

    // ---------------- Phase 3: epoch loop — templated NMS + periodic compaction ---------------
    float* ob = out_boxes  + (size_t)b * POST_TOPN * 4;
    float* os = out_scores + (size_t)b * POST_TOPN;

    int t = 0, ns = NSLOT, cur = 1, rc = 0;   // scores currently in skBuf1
    bool done = false;

    while (!done) {
        const int tEnd = (t + EPOCH < POST_TOPN) ? (t + EPOCH) : POST_TOPN;
        const float* skCur = cur ? skBuf1 : skBuf0;

        switch (ns) {
            case 24: t = run_epoch<24>(s, skCur, box, ab7, mask, t, tEnd, ob, os, tid, lane, warp, rc, done); break;
            case 18: t = run_epoch<18>(s, skCur, box, ab7, mask, t, tEnd, ob, os, tid, lane, warp, rc, done); break;
            case 14: t = run_epoch<14>(s, skCur, box, ab7, mask, t, tEnd, ob, os, tid, lane, warp, rc, done); break;
            case 12: t = run_epoch<12>(s, skCur, box, ab7, mask, t, tEnd, ob, os, tid, lane, warp, rc, done); break;
            case 10: t = run_epoch<10>(s, skCur, box, ab7, mask, t, tEnd, ob, os, tid, lane, warp, rc, done); break;
            case  8: t = run_epoch< 8>(s, skCur, box, ab7, mask, t, tEnd, ob, os, tid, lane, warp, rc, done); break;
            case  6: t = run_epoch< 6>(s, skCur, box, ab7, mask, t, tEnd, ob, os, tid, lane, warp, rc, done); break;
            case  4: t = run_epoch< 4>(s, skCur, box, ab7, mask, t, tEnd, ob, os, tid, lane, warp, rc, done); break;
            default: t = run_epoch< 2>(s, skCur, box, ab7, mask, t, tEnd, ob, os, tid, lane, warp, rc, done); break;
        }
        if (done) break;

        // ---- compaction: dense re-pack of live candidates (order preserved) ----
        float* skNext = cur ? skBuf0 : skBuf1;

        #pragma unroll
        for (int k = 0; k < NSLOT; ++k) {
            unsigned bal = __ballot_sync(fullm, (mask >> k) & 1u);
            if (lane == 0) s->hist[k * NWARP + warp] = __popc(bal);
        }
        __syncthreads();   // all threads done reading rbox/skCur this epoch
        if (tid == 0) {
            int run = 0;
            for (int i = 0; i < NSLOT * NWARP; ++i) { int v = s->hist[i]; s->hist[i] = run; run += v; }
            s->cnt = run;
        }
        __syncthreads();
        const int live = s->cnt;

        #pragma unroll
        for (int k = 0; k < NSLOT; ++k) {
            unsigned bit = (mask >> k) & 1u;
            unsigned bal = __ballot_sync(fullm, bit);
            if (bit) {
                int pos = s->hist[k * NWARP + warp] + __popc(bal & lml);
                skNext[pos]  = skCur[k * NT + tid];
                s->cbox[pos] = box[k];            // boxes re-packed from registers, in place
            }
        }
        __syncthreads();
        cur ^= 1;

        const int c = (live + NT - 1) / NT;
        ns = (c > 18) ? 24 : (c > 14) ? 18 : (c > 12) ? 14 : (c > 10) ? 12 :
             (c >  8) ? 10 : (c >  6) ?  8 : (c >  4) ?  6 : (c > 2) ? 4 : 2;
        mask = 0;
        #pragma unroll
        for (int k = 0; k < NSLOT; ++k) {
            int idx = k * NT + tid;
            if (k < ns && idx < live) {
                float4 cc = s->cbox[idx];
                box[k] = cc;
                ab7[k] = 0.7f * ((cc.z - cc.x) * (cc.w - cc.y));
                mask |= (1u << k);
            }
        }
    }

    // zero-fill remaining slots (reference emits zeros once candidates are exhausted)
    for (int i = t * 4 + tid; i < POST_TOPN * 4; i += NT) ob[i] = 0.0f;
    for (int i = t + tid;     i < POST_TOPN;     i += NT) os[i] = 0.0f;
}

extern "C" void kernel_launch(void* const* d_in, const int* in_sizes, int n_in,
                              void* d_out, int out_size) {
    const float* deltas  = (const float*)d_in[0];   // [64,31,31,36] f32
    const float* probs   = (const float*)d_in[1];   // [64,31,31,9]  f32
    // d_in[2]: gt_labels int64 — unused
    const float* anchors = (const float*)d_in[3];   // [8649,4] f32

    float* out_boxes  = (float*)d_out;                                   // [64,1500,4]
    float* out_scores = (float*)d_out + (size_t)BATCH_N * POST_TOPN * 4; // [64,1500]

    const size_t smem_bytes = sizeof(Smem);
    cudaFuncSetAttribute(roibbox_kernel,
                         cudaFuncAttributeMaxDynamicSharedMemorySize,
                         (int)smem_bytes);

    roibbox_kernel<<<BATCH_N, NT, smem_bytes>>>(
        deltas, probs, anchors, out_boxes, out_scores);
}